// round 15
// baseline (speedup 1.0000x reference)
#include <cuda_runtime.h>
#include <cuda_bf16.h>
#include <cstdint>
#include <math_constants.h>

#define T_LEN    8192
#define L_WIN    64
#define TP_LEN   (T_LEN - L_WIN + 1)   // 8129
#define P_NUM    64
#define BS       32
#define TILE_M   128
#define PAD_LEFT 32
#define EPS      1e-6f
#define LOG2E    1.4426950408889634f

#define SA       72
#define SA_B     (SA * 2)                  // 144 B per B row
#define B_ROWS   72                        // 64 shapelets + 8 stats rows (ones/zeros)
#define B_BYTES  (P_NUM * SA_B)            // 9216 (copied from prep)
#define DYN_SMEM (B_ROWS * SA_B)           // 10368

// precomputed z-normed shapelets (bf16, ldsm row layout [64][SA])
__device__ __nv_bfloat16 g_Bs[P_NUM * SA];

__device__ __forceinline__ uint32_t smem_u32(const void* p) {
    uint32_t a;
    asm("{ .reg .u64 t; cvta.to.shared.u64 t, %1; cvt.u32.u64 %0, t; }"
        : "=r"(a) : "l"(p));
    return a;
}
__device__ __forceinline__ float ex2f(float v) {
    float r;
    asm("ex2.approx.f32 %0, %1;" : "=f"(r) : "f"(v));
    return r;
}
__device__ __forceinline__ void ldsm_x4(uint32_t& r0, uint32_t& r1,
                                        uint32_t& r2, uint32_t& r3, uint32_t addr) {
    asm volatile("ldmatrix.sync.aligned.m8n8.x4.shared.b16 {%0,%1,%2,%3}, [%4];"
                 : "=r"(r0), "=r"(r1), "=r"(r2), "=r"(r3) : "r"(addr));
}
__device__ __forceinline__ void ldsm_x2(uint32_t& r0, uint32_t& r1, uint32_t addr) {
    asm volatile("ldmatrix.sync.aligned.m8n8.x2.shared.b16 {%0,%1}, [%2];"
                 : "=r"(r0), "=r"(r1) : "r"(addr));
}
__device__ __forceinline__ void mma_16816_bf16(
    float* c, uint32_t a0, uint32_t a1, uint32_t a2, uint32_t a3,
    uint32_t b0, uint32_t b1)
{
    asm volatile(
        "mma.sync.aligned.m16n8k16.row.col.f32.bf16.bf16.f32 "
        "{%0,%1,%2,%3}, {%4,%5,%6,%7}, {%8,%9}, {%0,%1,%2,%3};"
        : "+f"(c[0]), "+f"(c[1]), "+f"(c[2]), "+f"(c[3])
        : "r"(a0), "r"(a1), "r"(a2), "r"(a3), "r"(b0), "r"(b1));
}

// ---------------------------------------------------------------------------
// Prep: z-normalize shapelets once (1 CTA); PDL-signal when done.
// ---------------------------------------------------------------------------
__global__ void __launch_bounds__(256)
prep_shapelets(const float* __restrict__ sh) {
    const int lane = threadIdx.x & 31;
    const int wrp  = threadIdx.x >> 5;
    #pragma unroll
    for (int i = 0; i < 8; i++) {
        const int r = wrp * 8 + i;
        float v0 = sh[r * 64 + lane];
        float v1 = sh[r * 64 + lane + 32];
        float a = v0 + v1;
        float c = fmaf(v0, v0, v1 * v1);
        #pragma unroll
        for (int m = 16; m > 0; m >>= 1) {
            a += __shfl_xor_sync(0xffffffffu, a, m);
            c += __shfl_xor_sync(0xffffffffu, c, m);
        }
        float mu  = a * (1.f / L_WIN);
        float var = fmaxf(c * (1.f / L_WIN) - mu * mu, 0.f);
        float inv = 1.f / fmaxf(sqrtf(var), EPS);
        g_Bs[r * SA + lane]      = __float2bfloat16((v0 - mu) * inv);
        g_Bs[r * SA + lane + 32] = __float2bfloat16((v1 - mu) * inv);
    }
    asm volatile("griddepcontrol.launch_dependents;" ::: "memory");
}

// ---------------------------------------------------------------------------
// Main: 128 windows x 64 shapelets per CTA. Window stats computed ON the
// tensor core (ones-column MMA with x and x^2 operands) BEFORE the PDL wait,
// overlapping the prep launch. act = exp2(2*inv*log2e*dot - 128*log2e).
// ---------------------------------------------------------------------------
__global__ void __launch_bounds__(256)
shapelet_hmma11_kernel(const float* __restrict__ x,
                       const float* __restrict__ sh,
                       float* __restrict__ out)
{
    extern __shared__ char dyn[];   // B tile: rows 0..63 shapelets, 64..71 stats

    __shared__ float    xs[194];
    __shared__ uint32_t xe[96],  xo[96];    // bf16x2 replicas of x
    __shared__ uint32_t xe2[96], xo2[96];   // bf16x2 replicas of x^2

    const int tid  = threadIdx.x;
    const int lane = tid & 31;
    const int wrp  = tid >> 5;
    const int b    = blockIdx.y;
    const int t0   = blockIdx.x * TILE_M;

    // ---- x segment load ----
    {
        const float* xb = x + (size_t)b * T_LEN;
        if (tid < 194) {
            float v = 0.f;
            if (tid < 192) {
                int i0 = t0 + tid;
                v = (i0 < T_LEN) ? xb[i0] : 0.f;
            }
            xs[tid] = v;
        }
    }
    // ---- stats B tile rows 64..71: row 64 = ones, rows 65..71 = 0 ----
    {
        uint32_t* srow = reinterpret_cast<uint32_t*>(dyn + 64 * SA_B);
        #pragma unroll
        for (int i = 0; i < 2; i++) {
            int idx = tid + i * 256;
            if (idx < 8 * (SA_B / 4)) {
                int r = idx / (SA_B / 4);
                int w = idx % (SA_B / 4);
                srow[idx] = (r == 0 && w < 32) ? 0x3F803F80u : 0u;
            }
        }
    }
    __syncthreads();

    // ---- bf16x2 replicas of x and x^2 ----
    if (tid < 96) {
        float a0 = xs[2 * tid], a1 = xs[2 * tid + 1], a2 = xs[2 * tid + 2];
        __nv_bfloat162 he = __floats2bfloat162_rn(a0, a1);
        __nv_bfloat162 ho = __floats2bfloat162_rn(a1, a2);
        xe[tid] = *reinterpret_cast<uint32_t*>(&he);
        xo[tid] = *reinterpret_cast<uint32_t*>(&ho);
        __nv_bfloat162 he2 = __floats2bfloat162_rn(a0 * a0, a1 * a1);
        __nv_bfloat162 ho2 = __floats2bfloat162_rn(a1 * a1, a2 * a2);
        xe2[tid] = *reinterpret_cast<uint32_t*>(&he2);
        xo2[tid] = *reinterpret_cast<uint32_t*>(&ho2);
    }
    __syncthreads();

    // ---- A fragments from replicas ----
    const int g  = lane >> 2;
    const int tq = lane & 3;
    const int s0 = wrp * 16 + g + tq * 2;
    const int w0 = s0 >> 1;
    uint32_t xw[9];
    {
        const uint32_t* src = (s0 & 1) ? xo : xe;
        #pragma unroll
        for (int j = 0; j < 9; j++) xw[j] = src[w0 + 4 * j];
    }

    const int rr = lane & 7;
    const int q  = lane >> 3;
    const uint32_t Bu = smem_u32(dyn);
    const uint32_t bAddr  = Bu + (uint32_t)(rr + (q >> 1) * 8) * SA_B
                               + (uint32_t)(q & 1) * 16;
    const uint32_t bAddrS = Bu + (uint32_t)(64 + rr) * SA_B
                               + (uint32_t)(q & 1) * 16;

    // ---- stats MMAs (prep-independent): sum(x), sum(x^2) per row ----
    float cS1[4] = {0.f, 0.f, 0.f, 0.f};
    float cS2[4] = {0.f, 0.f, 0.f, 0.f};
    {
        const uint32_t* src2 = (s0 & 1) ? xo2 : xe2;
        #pragma unroll
        for (int k = 0; k < 4; k++) {
            uint32_t b0, b1;
            ldsm_x2(b0, b1, bAddrS + (uint32_t)k * 32);
            mma_16816_bf16(cS1, xw[2 * k], xw[2 * k + 1], xw[2 * k + 1], xw[2 * k + 2], b0, b1);
            uint32_t q0 = src2[w0 + 8 * k];
            uint32_t q1 = src2[w0 + 8 * k + 4];
            uint32_t q2 = src2[w0 + 8 * k + 8];
            mma_16816_bf16(cS2, q0, q1, q1, q2, b0, b1);
        }
    }
    // per-half inv (broadcast col-64 values from tq=0 lane of each quad)
    float minv[2];
    #pragma unroll
    for (int half = 0; half < 2; half++) {
        float sm = __shfl_sync(0xffffffffu, cS1[half * 2], lane & ~3);
        float sq = __shfl_sync(0xffffffffu, cS2[half * 2], lane & ~3);
        float mu  = sm * (1.f / L_WIN);
        float var = fmaf(-mu, mu, sq * (1.f / L_WIN));
        minv[half] = rsqrtf(fmaxf(var, 1e-12f));
    }

    // ---- wait for prep; copy shapelet B tile ----
    asm volatile("griddepcontrol.wait;" ::: "memory");
    {
        const uint4* gB = reinterpret_cast<const uint4*>(g_Bs);
        uint4*       sB = reinterpret_cast<uint4*>(dyn);
        #pragma unroll
        for (int i = 0; i < 3; i++) {
            int idx = tid + i * 256;
            if (idx < (B_BYTES / 16)) sB[idx] = gB[idx];
        }
    }
    __syncthreads();

    // ---- main MMAs (warp owns rows 16*wrp..+15) ----
    float c[8][4];
    #pragma unroll
    for (int nt = 0; nt < 8; nt++)
        #pragma unroll
        for (int r = 0; r < 4; r++) c[nt][r] = 0.f;

    #pragma unroll
    for (int k = 0; k < 4; k++) {
        const uint32_t a0 = xw[2 * k], a12 = xw[2 * k + 1], a3 = xw[2 * k + 2];
        #pragma unroll
        for (int nt2 = 0; nt2 < 4; nt2++) {
            uint32_t b0, b1, b2, b3;
            ldsm_x4(b0, b1, b2, b3,
                    bAddr + (uint32_t)nt2 * (16 * SA_B) + (uint32_t)k * 32);
            mma_16816_bf16(c[2 * nt2],     a0, a12, a12, a3, b0, b1);
            mma_16816_bf16(c[2 * nt2 + 1], a0, a12, a12, a3, b2, b3);
        }
    }

    // ---- epilogue: act = ex2(m*dot + cst); shfl pair-exchange; STG.128 ----
    {
        float* outb = out + (size_t)b * T_LEN * P_NUM;
        #pragma unroll
        for (int half = 0; half < 2; half++) {
            const int rowL = wrp * 16 + g + half * 8;
            const int tout = t0 + rowL + PAD_LEFT;
            const bool ok  = (t0 + rowL) < TP_LEN;
            const float m   = ok ? minv[half] * (2.f * LOG2E) : 0.f;
            const float cst = ok ? (-128.f * LOG2E) : -CUDART_INF_F;
            float2 e[8];
            #pragma unroll
            for (int nt = 0; nt < 8; nt++) {
                e[nt].x = ex2f(fmaf(m, c[nt][half * 2 + 0], cst));
                e[nt].y = ex2f(fmaf(m, c[nt][half * 2 + 1], cst));
            }
            float* orow = outb + (size_t)tout * P_NUM;
            #pragma unroll
            for (int j = 0; j < 4; j++) {
                const int nt0 = 2 * j, nt1 = 2 * j + 1;
                float2 send = (tq & 1) ? e[nt0] : e[nt1];
                long long sl; memcpy(&sl, &send, 8);
                long long rl = __shfl_xor_sync(0xffffffffu, sl, 1);
                float2 recv; memcpy(&recv, &rl, 8);
                float2 own = (tq & 1) ? e[nt1] : e[nt0];
                float4 v = (tq & 1)
                    ? make_float4(recv.x, recv.y, own.x, own.y)
                    : make_float4(own.x, own.y, recv.x, recv.y);
                const int col = ((tq & 1) ? nt1 : nt0) * 8 + (tq & 2) * 2;
                if (tout < T_LEN)
                    *reinterpret_cast<float4*>(orow + col) = v;
            }
        }
        // left pad rows [0,32): zeros (tile 0 only)
        if (blockIdx.x == 0) {
            float4 z = make_float4(0.f, 0.f, 0.f, 0.f);
            #pragma unroll
            for (int it = 0; it < 2; it++) {
                int qq  = tid + it * 256;
                int row = qq >> 4;
                int c4  = qq & 15;
                *reinterpret_cast<float4*>(outb + (size_t)row * P_NUM + c4 * 4) = z;
            }
        }
    }
}

extern "C" void kernel_launch(void* const* d_in, const int* in_sizes, int n_in,
                              void* d_out, int out_size) {
    const float* x  = (const float*)d_in[0];   // (32, 8192, 1)
    const float* sh = (const float*)d_in[1];   // (64, 1, 64)
    float* out = (float*)d_out;                // (32, 8192, 64)

    prep_shapelets<<<1, 256>>>(sh);

    cudaFuncSetAttribute(shapelet_hmma11_kernel,
                         cudaFuncAttributeMaxDynamicSharedMemorySize, DYN_SMEM);

    cudaLaunchAttribute attrs[1];
    attrs[0].id = cudaLaunchAttributeProgrammaticStreamSerialization;
    attrs[0].val.programmaticStreamSerializationAllowed = 1;

    cudaLaunchConfig_t cfg = {};
    cfg.gridDim  = dim3((TP_LEN + TILE_M - 1) / TILE_M, BS);   // (64, 32)
    cfg.blockDim = dim3(256, 1, 1);
    cfg.dynamicSmemBytes = DYN_SMEM;
    cfg.attrs    = attrs;
    cfg.numAttrs = 1;
    cudaLaunchKernelEx(&cfg, shapelet_hmma11_kernel, x, sh, out);
}